// round 8
// baseline (speedup 1.0000x reference)
#include <cuda_runtime.h>

// Pull_37091337568590, R8: channel-pair (float2) interleaved smem tiles.
// Each LDS.64 tap yields both channels of the pair -> half the tap count.
// Fill = LDG.128 x2 planes -> interleave -> STS.128 x2, pipelined one stage
// ahead (LDG latency hidden behind the previous stage's blend).
// x: [8,16,512,512] f32, phi: [8,2,512,512] f32, out: [8,16,512,512] f32.

#define PB 8
#define PC 16
#define PH 512
#define PW 512
#define PHW (PH * PW)

#define TW 64
#define TH 32
#define HR 8
#define SW (TW + 2 * HR)       // 80 pixels per tile row
#define SH (TH + 2 * HR)       // 48 rows
#define S2 82                  // row stride in float2 units (even -> 16B align)
#define TILE_F2 (SH * S2)      // 3936 float2 per buffer
#define NT 512
#define NPPT 4                 // pixels per thread (64*32/512)
#define NST (PC / 2)           // 8 channel-pair stages
#define FSLOTS (SH * (SW / 4)) // 960 float4 fill slots per plane

__global__ __launch_bounds__(NT)
void pull_pair_kernel(const float* __restrict__ x,
                      const float* __restrict__ phi,
                      float* __restrict__ out)
{
    extern __shared__ float2 smem2[];
    float2* bufA = smem2;
    float2* bufB = smem2 + TILE_F2;

    const int tx0 = blockIdx.x * TW;
    const int ty0 = blockIdx.y * TH;
    const int b   = blockIdx.z;
    const int tid = threadIdx.x;

    const int px = tid & (TW - 1);   // 0..63
    const int py = tid >> 6;         // 0..7

    const float* __restrict__ phiy = phi + (size_t)b * 2 * PHW;
    const float* __restrict__ phix = phiy + PHW;
    const float* __restrict__ xb   = x   + (size_t)b * PC * PHW;
    float* __restrict__ ob         = out + (size_t)b * PC * PHW;

    // ---- per-pixel coords in registers (4 px/thread, rows py + 8i) ----
    unsigned sel[NPPT];
    float    fwy[NPPT], fwx[NPPT];
    #pragma unroll
    for (int i = 0; i < NPPT; i++) {
        int ly = py + i * 8;
        int h  = ty0 + ly;
        int w  = tx0 + px;
        int p  = h * PW + w;

        float cy = __ldg(phiy + p) + (float)h;
        float cx = __ldg(phix + p) + (float)w;
        float y0f = floorf(cy);
        float x0f = floorf(cx);
        fwy[i] = cy - y0f;
        fwx[i] = cx - x0f;

        int y0 = (int)y0f;
        int x0 = (int)x0f;
        int sy = y0 - (ty0 - HR);
        int sx = x0 - (tx0 - HR);

        if ((unsigned)sy < (SH - 1) && (unsigned)sx < (SW - 1)) {
            sel[i] = (unsigned)((sy * S2 + sx) * 8);        // byte offset (float2)
        } else {
            sel[i] = 0x80000000u | ((unsigned)(y0 & (PH - 1)) << 9)
                                 |  (unsigned)(x0 & (PW - 1));
        }
    }

    // ---- fill mapping (constant per thread): 2 passes over 960 float4 slots --
    const int slot0 = tid;
    const int slot1 = tid + NT;
    const bool act1 = (slot1 < FSLOTS);
    const int r0 = slot0 / 20, c40 = slot0 - r0 * 20;
    const int r1 = slot1 / 20, c41 = slot1 - r1 * 20;
    const int goff0 = (((ty0 - HR + r0) & (PH - 1)) * PW)
                    +  ((tx0 - HR + c40 * 4) & (PW - 1));
    const int goff1 = (((ty0 - HR + r1) & (PH - 1)) * PW)
                    +  ((tx0 - HR + c41 * 4) & (PW - 1));
    const int d0 = r0 * S2 + c40 * 4;        // float2 index in tile
    const int d1 = r1 * S2 + c41 * 4;

    float4 fa0, fb0, fa1, fb1;               // fill data regs (one stage ahead)

    auto fill_ldg = [&](int stage) {
        const float* p0 = xb + (size_t)(2 * stage) * PHW;
        const float* p1 = p0 + PHW;
        fa0 = *(const float4*)(p0 + goff0);
        fb0 = *(const float4*)(p1 + goff0);
        if (act1) {
            fa1 = *(const float4*)(p0 + goff1);
            fb1 = *(const float4*)(p1 + goff1);
        }
    };
    auto fill_sts = [&](float2* buf) {
        *(float4*)(buf + d0)     = make_float4(fa0.x, fb0.x, fa0.y, fb0.y);
        *(float4*)(buf + d0 + 2) = make_float4(fa0.z, fb0.z, fa0.w, fb0.w);
        if (act1) {
            *(float4*)(buf + d1)     = make_float4(fa1.x, fb1.x, fa1.y, fb1.y);
            *(float4*)(buf + d1 + 2) = make_float4(fa1.z, fb1.z, fa1.w, fb1.w);
        }
    };

    const int pbase = (ty0 + py) * PW + tx0 + px;

    // ---- prologue ----
    fill_ldg(0);
    fill_sts(bufA);          // exposed latency once per block
    fill_ldg(1);             // in flight during first blend
    __syncthreads();

    #pragma unroll
    for (int s = 0; s < NST; s++) {
        const float2* __restrict__ cur = (s & 1) ? bufB : bufA;
        const float* __restrict__ c0 = xb + (size_t)(2 * s) * PHW;
        const float* __restrict__ c1 = c0 + PHW;
        float* __restrict__ o0 = ob + (size_t)(2 * s) * PHW;
        float* __restrict__ o1 = o0 + PHW;

        #pragma unroll
        for (int i = 0; i < NPPT; i++) {
            unsigned sl = sel[i];
            float wy = fwy[i];
            float wx = fwx[i];

            float2 v00, v01, v10, v11;
            if (!(sl & 0x80000000u)) {
                const float2* t = (const float2*)((const char*)cur + sl);
                v00 = t[0];
                v01 = t[1];
                v10 = t[S2];
                v11 = t[S2 + 1];
            } else {
                int y0 = (int)((sl >> 9) & (PH - 1));
                int x0 = (int)(sl & (PW - 1));
                int y1 = (y0 + 1) & (PH - 1);
                int x1 = (x0 + 1) & (PW - 1);
                int a = y0 * PW + x0, bq = y0 * PW + x1;
                int cq = y1 * PW + x0, d = y1 * PW + x1;
                v00 = make_float2(__ldg(c0 + a),  __ldg(c1 + a));
                v01 = make_float2(__ldg(c0 + bq), __ldg(c1 + bq));
                v10 = make_float2(__ldg(c0 + cq), __ldg(c1 + cq));
                v11 = make_float2(__ldg(c0 + d),  __ldg(c1 + d));
            }

            float tx_ = v00.x + wx * (v01.x - v00.x);
            float bx_ = v10.x + wx * (v11.x - v10.x);
            float ty_ = v00.y + wx * (v01.y - v00.y);
            float by_ = v10.y + wx * (v11.y - v10.y);
            float rx = tx_ + wy * (bx_ - tx_);
            float ry = ty_ + wy * (by_ - ty_);

            int p = pbase + i * 8 * PW;
            o0[p] = rx;
            o1[p] = ry;
        }

        if (s < NST - 1) {
            __syncthreads();                       // readers of other buf done
            fill_sts((s & 1) ? bufA : bufB);       // stage s+1 (regs from s-1)
            if (s + 2 < NST) fill_ldg(s + 2);      // prefetch stage s+2
            __syncthreads();                       // fill visible before blend
        }
    }
}

extern "C" void kernel_launch(void* const* d_in, const int* in_sizes, int n_in,
                              void* d_out, int out_size)
{
    const float* x   = (const float*)d_in[0];
    const float* phi = (const float*)d_in[1];
    float* out = (float*)d_out;

    const int smem_bytes = 2 * TILE_F2 * sizeof(float2);   // 62976 B
    static int configured = -1;
    if (configured < 0) {
        cudaFuncSetAttribute(pull_pair_kernel,
                             cudaFuncAttributeMaxDynamicSharedMemorySize,
                             smem_bytes);
        configured = 1;
    }

    dim3 grid(PW / TW, PH / TH, PB);   // 8 x 16 x 8 = 1024 blocks
    pull_pair_kernel<<<grid, NT, smem_bytes>>>(x, phi, out);
}

// round 9
// speedup vs baseline: 1.1777x; 1.1777x over previous
#include <cuda_runtime.h>
#include <cuda_fp16.h>

// Pull_37091337568590, R9: fp16 channel-quad smem tiles.
// Tile stores 4 channels per pixel as 4 x fp16 (uint2, 8B). One LDS.64 tap
// -> 4 channels: crossbar bytes per output halved vs R8. f32 accumulation;
// fallback (outside halo) gathers f32 from gmem. 4 stages of 4 channels,
// double-buffered, fill pipelined one stage ahead (LDG f32 -> cvt/pack ->
// STS.128).
// x: [8,16,512,512] f32, phi: [8,2,512,512] f32, out: [8,16,512,512] f32.

#define PB 8
#define PC 16
#define PH 512
#define PW 512
#define PHW (PH * PW)

#define TW 64
#define TH 32
#define HR 8
#define SW (TW + 2 * HR)       // 80 pixels per tile row
#define SH (TH + 2 * HR)       // 48 rows
#define SU 80                  // row stride in uint2 (640B: bank shift 0 mod 32)
#define TILE_U2 (SH * SU)      // 3840 uint2 per buffer (30720 B)
#define NT 512
#define NPPT 4                 // pixels per thread
#define NST 4                  // 4 channel-quad stages
#define FSLOTS (SH * (SW / 4)) // 960 float4 fill slots

__device__ __forceinline__ unsigned pk(float a, float b) {
    __half2 h = __floats2half2_rn(a, b);
    return *(unsigned*)&h;
}
__device__ __forceinline__ float2 up(unsigned u) {
    return __half22float2(*(__half2*)&u);
}

__global__ __launch_bounds__(NT, 2)
void pull_h4_kernel(const float* __restrict__ x,
                    const float* __restrict__ phi,
                    float* __restrict__ out)
{
    extern __shared__ uint2 smemu[];
    uint2* bufA = smemu;
    uint2* bufB = smemu + TILE_U2;

    const int tx0 = blockIdx.x * TW;
    const int ty0 = blockIdx.y * TH;
    const int b   = blockIdx.z;
    const int tid = threadIdx.x;

    const int px = tid & (TW - 1);   // 0..63
    const int py = tid >> 6;         // 0..7

    const float* __restrict__ phiy = phi + (size_t)b * 2 * PHW;
    const float* __restrict__ phix = phiy + PHW;
    const float* __restrict__ xb   = x   + (size_t)b * PC * PHW;
    float* __restrict__ ob         = out + (size_t)b * PC * PHW;

    // ---- per-pixel coords in registers (rows py + 8i) ----
    unsigned sel[NPPT];
    float    fwy[NPPT], fwx[NPPT];
    #pragma unroll
    for (int i = 0; i < NPPT; i++) {
        int ly = py + i * 8;
        int h  = ty0 + ly;
        int w  = tx0 + px;
        int p  = h * PW + w;

        float cy = __ldg(phiy + p) + (float)h;
        float cx = __ldg(phix + p) + (float)w;
        float y0f = floorf(cy);
        float x0f = floorf(cx);
        fwy[i] = cy - y0f;
        fwx[i] = cx - x0f;

        int y0 = (int)y0f;
        int x0 = (int)x0f;
        int sy = y0 - (ty0 - HR);
        int sx = x0 - (tx0 - HR);

        if ((unsigned)sy < (SH - 1) && (unsigned)sx < (SW - 1)) {
            sel[i] = (unsigned)((sy * SU + sx) * 8);        // byte offset (uint2)
        } else {
            sel[i] = 0x80000000u | ((unsigned)(y0 & (PH - 1)) << 9)
                                 |  (unsigned)(x0 & (PW - 1));
        }
    }

    // ---- fill mapping: 960 float4 slots, 2 passes ----
    const int slot0 = tid;
    const int slot1 = tid + NT;
    const bool act1 = (slot1 < FSLOTS);
    const int r0 = slot0 / 20, c40 = slot0 - r0 * 20;
    const int r1 = slot1 / 20, c41 = slot1 - r1 * 20;
    const int goff0 = (((ty0 - HR + r0) & (PH - 1)) * PW)
                    +  ((tx0 - HR + c40 * 4) & (PW - 1));
    const int goff1 = (((ty0 - HR + r1) & (PH - 1)) * PW)
                    +  ((tx0 - HR + c41 * 4) & (PW - 1));
    const int d0 = r0 * SU + c40 * 4;        // uint2 index in tile
    const int d1 = r1 * SU + c41 * 4;

    uint2 h0[4], h1[4];                      // packed fill regs (held one stage)

    auto fill_ldg = [&](int st) {
        const float* base = xb + (size_t)(4 * st) * PHW;
        {
            float4 a = *(const float4*)(base + goff0);
            float4 bq = *(const float4*)(base + PHW + goff0);
            float4 c = *(const float4*)(base + 2 * PHW + goff0);
            float4 d = *(const float4*)(base + 3 * PHW + goff0);
            h0[0] = make_uint2(pk(a.x, bq.x), pk(c.x, d.x));
            h0[1] = make_uint2(pk(a.y, bq.y), pk(c.y, d.y));
            h0[2] = make_uint2(pk(a.z, bq.z), pk(c.z, d.z));
            h0[3] = make_uint2(pk(a.w, bq.w), pk(c.w, d.w));
        }
        if (act1) {
            float4 a = *(const float4*)(base + goff1);
            float4 bq = *(const float4*)(base + PHW + goff1);
            float4 c = *(const float4*)(base + 2 * PHW + goff1);
            float4 d = *(const float4*)(base + 3 * PHW + goff1);
            h1[0] = make_uint2(pk(a.x, bq.x), pk(c.x, d.x));
            h1[1] = make_uint2(pk(a.y, bq.y), pk(c.y, d.y));
            h1[2] = make_uint2(pk(a.z, bq.z), pk(c.z, d.z));
            h1[3] = make_uint2(pk(a.w, bq.w), pk(c.w, d.w));
        }
    };
    auto fill_sts = [&](uint2* buf) {
        *(uint4*)(buf + d0)     = make_uint4(h0[0].x, h0[0].y, h0[1].x, h0[1].y);
        *(uint4*)(buf + d0 + 2) = make_uint4(h0[2].x, h0[2].y, h0[3].x, h0[3].y);
        if (act1) {
            *(uint4*)(buf + d1)     = make_uint4(h1[0].x, h1[0].y, h1[1].x, h1[1].y);
            *(uint4*)(buf + d1 + 2) = make_uint4(h1[2].x, h1[2].y, h1[3].x, h1[3].y);
        }
    };

    const int pbase = (ty0 + py) * PW + tx0 + px;

    // ---- prologue ----
    fill_ldg(0);
    fill_sts(bufA);
    fill_ldg(1);             // in flight during first blend
    __syncthreads();

    #pragma unroll
    for (int st = 0; st < NST; st++) {
        const uint2* __restrict__ cur = (st & 1) ? bufB : bufA;
        const float* __restrict__ c0 = xb + (size_t)(4 * st) * PHW;
        float* __restrict__ o0       = ob + (size_t)(4 * st) * PHW;

        #pragma unroll
        for (int i = 0; i < NPPT; i++) {
            unsigned sl = sel[i];
            float wy = fwy[i];
            float wx = fwx[i];

            float2 A00, A01, A10, A11;   // ch 0,1
            float2 B00, B01, B10, B11;   // ch 2,3
            if (!(sl & 0x80000000u)) {
                const uint2* t = (const uint2*)((const char*)cur + sl);
                uint2 v00 = t[0], v01 = t[1], v10 = t[SU], v11 = t[SU + 1];
                A00 = up(v00.x); B00 = up(v00.y);
                A01 = up(v01.x); B01 = up(v01.y);
                A10 = up(v10.x); B10 = up(v10.y);
                A11 = up(v11.x); B11 = up(v11.y);
            } else {
                int y0 = (int)((sl >> 9) & (PH - 1));
                int x0 = (int)(sl & (PW - 1));
                int y1 = (y0 + 1) & (PH - 1);
                int x1 = (x0 + 1) & (PW - 1);
                int a = y0 * PW + x0, bq = y0 * PW + x1;
                int cq = y1 * PW + x0, d = y1 * PW + x1;
                A00 = make_float2(__ldg(c0 + a),           __ldg(c0 + PHW + a));
                A01 = make_float2(__ldg(c0 + bq),          __ldg(c0 + PHW + bq));
                A10 = make_float2(__ldg(c0 + cq),          __ldg(c0 + PHW + cq));
                A11 = make_float2(__ldg(c0 + d),           __ldg(c0 + PHW + d));
                B00 = make_float2(__ldg(c0 + 2 * PHW + a), __ldg(c0 + 3 * PHW + a));
                B01 = make_float2(__ldg(c0 + 2 * PHW + bq),__ldg(c0 + 3 * PHW + bq));
                B10 = make_float2(__ldg(c0 + 2 * PHW + cq),__ldg(c0 + 3 * PHW + cq));
                B11 = make_float2(__ldg(c0 + 2 * PHW + d), __ldg(c0 + 3 * PHW + d));
            }

            float ta0 = A00.x + wx * (A01.x - A00.x);
            float ba0 = A10.x + wx * (A11.x - A10.x);
            float ta1 = A00.y + wx * (A01.y - A00.y);
            float ba1 = A10.y + wx * (A11.y - A10.y);
            float tb0 = B00.x + wx * (B01.x - B00.x);
            float bb0 = B10.x + wx * (B11.x - B10.x);
            float tb1 = B00.y + wx * (B01.y - B00.y);
            float bb1 = B10.y + wx * (B11.y - B10.y);

            int p = pbase + i * 8 * PW;
            o0[p]           = ta0 + wy * (ba0 - ta0);
            o0[PHW + p]     = ta1 + wy * (ba1 - ta1);
            o0[2 * PHW + p] = tb0 + wy * (bb0 - tb0);
            o0[3 * PHW + p] = tb1 + wy * (bb1 - tb1);
        }

        if (st < NST - 1) {
            __syncthreads();                        // readers of other buf done
            fill_sts((st & 1) ? bufA : bufB);       // stage st+1
            if (st + 2 < NST) fill_ldg(st + 2);     // prefetch stage st+2
            __syncthreads();                        // fill visible before blend
        }
    }
}

extern "C" void kernel_launch(void* const* d_in, const int* in_sizes, int n_in,
                              void* d_out, int out_size)
{
    const float* x   = (const float*)d_in[0];
    const float* phi = (const float*)d_in[1];
    float* out = (float*)d_out;

    const int smem_bytes = 2 * TILE_U2 * sizeof(uint2);   // 61440 B
    static int configured = -1;
    if (configured < 0) {
        cudaFuncSetAttribute(pull_h4_kernel,
                             cudaFuncAttributeMaxDynamicSharedMemorySize,
                             smem_bytes);
        configured = 1;
    }

    dim3 grid(PW / TW, PH / TH, PB);   // 8 x 16 x 8 = 1024 blocks
    pull_h4_kernel<<<grid, NT, smem_bytes>>>(x, phi, out);
}

// round 10
// speedup vs baseline: 1.2928x; 1.0978x over previous
#include <cuda_runtime.h>
#include <cuda_fp16.h>

// Pull_37091337568590, R10: R9 (fp16 channel-quad tiles) + x-paired pixels:
// each thread owns pixel pair (2u, 2u+1) -> STG.64 stores (half the store
// instrs) and float2 phi loads. 4 stages of 4 channels, double-buffered,
// fill pipelined one stage ahead.
// x: [8,16,512,512] f32, phi: [8,2,512,512] f32, out: [8,16,512,512] f32.

#define PB 8
#define PC 16
#define PH 512
#define PW 512
#define PHW (PH * PW)

#define TW 64
#define TH 32
#define HR 8
#define SW (TW + 2 * HR)       // 80 pixels per tile row
#define SH (TH + 2 * HR)       // 48 rows
#define SU 80                  // row stride in uint2
#define TILE_U2 (SH * SU)      // 3840 uint2 per buffer (30720 B)
#define NT 512
#define NRI 2                  // row iterations per thread (x2 px each = 4 px)
#define NST 4                  // 4 channel-quad stages
#define FSLOTS (SH * (SW / 4)) // 960 float4 fill slots

__device__ __forceinline__ unsigned pk(float a, float b) {
    __half2 h = __floats2half2_rn(a, b);
    return *(unsigned*)&h;
}
__device__ __forceinline__ float2 up(unsigned u) {
    return __half22float2(*(__half2*)&u);
}

__global__ __launch_bounds__(NT, 2)
void pull_h4p_kernel(const float* __restrict__ x,
                     const float* __restrict__ phi,
                     float* __restrict__ out)
{
    extern __shared__ uint2 smemu[];
    uint2* bufA = smemu;
    uint2* bufB = smemu + TILE_U2;

    const int tx0 = blockIdx.x * TW;
    const int ty0 = blockIdx.y * TH;
    const int b   = blockIdx.z;
    const int tid = threadIdx.x;

    const int u  = tid & 31;         // x-pair index: pixels 2u, 2u+1
    const int py = tid >> 5;         // 0..15

    const float* __restrict__ phiy = phi + (size_t)b * 2 * PHW;
    const float* __restrict__ phix = phiy + PHW;
    const float* __restrict__ xb   = x   + (size_t)b * PC * PHW;
    float* __restrict__ ob         = out + (size_t)b * PC * PHW;

    // ---- per-pixel coords in registers: 2 row-iters x 2 px ----
    unsigned sel[NRI * 2];
    float    fwy[NRI * 2], fwx[NRI * 2];
    #pragma unroll
    for (int i = 0; i < NRI; i++) {
        int ly = py + i * 16;
        int h  = ty0 + ly;
        int wb = tx0 + 2 * u;
        int p  = h * PW + wb;

        float2 dy2 = __ldg((const float2*)(phiy + p));
        float2 dx2 = __ldg((const float2*)(phix + p));

        #pragma unroll
        for (int j = 0; j < 2; j++) {
            float cy = (j ? dy2.y : dy2.x) + (float)h;
            float cx = (j ? dx2.y : dx2.x) + (float)(wb + j);
            float y0f = floorf(cy);
            float x0f = floorf(cx);
            int k = i * 2 + j;
            fwy[k] = cy - y0f;
            fwx[k] = cx - x0f;

            int y0 = (int)y0f;
            int x0 = (int)x0f;
            int sy = y0 - (ty0 - HR);
            int sx = x0 - (tx0 - HR);

            if ((unsigned)sy < (SH - 1) && (unsigned)sx < (SW - 1)) {
                sel[k] = (unsigned)((sy * SU + sx) * 8);    // byte offset (uint2)
            } else {
                sel[k] = 0x80000000u | ((unsigned)(y0 & (PH - 1)) << 9)
                                     |  (unsigned)(x0 & (PW - 1));
            }
        }
    }

    // ---- fill mapping: 960 float4 slots, 2 passes ----
    const int slot0 = tid;
    const int slot1 = tid + NT;
    const bool act1 = (slot1 < FSLOTS);
    const int r0 = slot0 / 20, c40 = slot0 - r0 * 20;
    const int r1 = slot1 / 20, c41 = slot1 - r1 * 20;
    const int goff0 = (((ty0 - HR + r0) & (PH - 1)) * PW)
                    +  ((tx0 - HR + c40 * 4) & (PW - 1));
    const int goff1 = (((ty0 - HR + r1) & (PH - 1)) * PW)
                    +  ((tx0 - HR + c41 * 4) & (PW - 1));
    const int d0 = r0 * SU + c40 * 4;
    const int d1 = r1 * SU + c41 * 4;

    uint2 h0[4], h1[4];

    auto fill_ldg = [&](int st) {
        const float* base = xb + (size_t)(4 * st) * PHW;
        {
            float4 a  = *(const float4*)(base + goff0);
            float4 bq = *(const float4*)(base + PHW + goff0);
            float4 c  = *(const float4*)(base + 2 * PHW + goff0);
            float4 d  = *(const float4*)(base + 3 * PHW + goff0);
            h0[0] = make_uint2(pk(a.x, bq.x), pk(c.x, d.x));
            h0[1] = make_uint2(pk(a.y, bq.y), pk(c.y, d.y));
            h0[2] = make_uint2(pk(a.z, bq.z), pk(c.z, d.z));
            h0[3] = make_uint2(pk(a.w, bq.w), pk(c.w, d.w));
        }
        if (act1) {
            float4 a  = *(const float4*)(base + goff1);
            float4 bq = *(const float4*)(base + PHW + goff1);
            float4 c  = *(const float4*)(base + 2 * PHW + goff1);
            float4 d  = *(const float4*)(base + 3 * PHW + goff1);
            h1[0] = make_uint2(pk(a.x, bq.x), pk(c.x, d.x));
            h1[1] = make_uint2(pk(a.y, bq.y), pk(c.y, d.y));
            h1[2] = make_uint2(pk(a.z, bq.z), pk(c.z, d.z));
            h1[3] = make_uint2(pk(a.w, bq.w), pk(c.w, d.w));
        }
    };
    auto fill_sts = [&](uint2* buf) {
        *(uint4*)(buf + d0)     = make_uint4(h0[0].x, h0[0].y, h0[1].x, h0[1].y);
        *(uint4*)(buf + d0 + 2) = make_uint4(h0[2].x, h0[2].y, h0[3].x, h0[3].y);
        if (act1) {
            *(uint4*)(buf + d1)     = make_uint4(h1[0].x, h1[0].y, h1[1].x, h1[1].y);
            *(uint4*)(buf + d1 + 2) = make_uint4(h1[2].x, h1[2].y, h1[3].x, h1[3].y);
        }
    };

    // ---- prologue ----
    fill_ldg(0);
    fill_sts(bufA);
    fill_ldg(1);
    __syncthreads();

    #pragma unroll
    for (int st = 0; st < NST; st++) {
        const uint2* __restrict__ cur = (st & 1) ? bufB : bufA;
        const float* __restrict__ c0 = xb + (size_t)(4 * st) * PHW;
        float* __restrict__ o0       = ob + (size_t)(4 * st) * PHW;

        #pragma unroll
        for (int i = 0; i < NRI; i++) {
            float r[4][2];                       // [channel][px in pair]
            #pragma unroll
            for (int j = 0; j < 2; j++) {
                int k = i * 2 + j;
                unsigned sl = sel[k];
                float wy = fwy[k];
                float wx = fwx[k];

                float2 A00, A01, A10, A11;       // ch 0,1
                float2 B00, B01, B10, B11;       // ch 2,3
                if (!(sl & 0x80000000u)) {
                    const uint2* t = (const uint2*)((const char*)cur + sl);
                    uint2 v00 = t[0], v01 = t[1], v10 = t[SU], v11 = t[SU + 1];
                    A00 = up(v00.x); B00 = up(v00.y);
                    A01 = up(v01.x); B01 = up(v01.y);
                    A10 = up(v10.x); B10 = up(v10.y);
                    A11 = up(v11.x); B11 = up(v11.y);
                } else {
                    int y0 = (int)((sl >> 9) & (PH - 1));
                    int x0 = (int)(sl & (PW - 1));
                    int y1 = (y0 + 1) & (PH - 1);
                    int x1 = (x0 + 1) & (PW - 1);
                    int a = y0 * PW + x0, bq = y0 * PW + x1;
                    int cq = y1 * PW + x0, d = y1 * PW + x1;
                    A00 = make_float2(__ldg(c0 + a),            __ldg(c0 + PHW + a));
                    A01 = make_float2(__ldg(c0 + bq),           __ldg(c0 + PHW + bq));
                    A10 = make_float2(__ldg(c0 + cq),           __ldg(c0 + PHW + cq));
                    A11 = make_float2(__ldg(c0 + d),            __ldg(c0 + PHW + d));
                    B00 = make_float2(__ldg(c0 + 2 * PHW + a),  __ldg(c0 + 3 * PHW + a));
                    B01 = make_float2(__ldg(c0 + 2 * PHW + bq), __ldg(c0 + 3 * PHW + bq));
                    B10 = make_float2(__ldg(c0 + 2 * PHW + cq), __ldg(c0 + 3 * PHW + cq));
                    B11 = make_float2(__ldg(c0 + 2 * PHW + d),  __ldg(c0 + 3 * PHW + d));
                }

                float ta0 = A00.x + wx * (A01.x - A00.x);
                float ba0 = A10.x + wx * (A11.x - A10.x);
                float ta1 = A00.y + wx * (A01.y - A00.y);
                float ba1 = A10.y + wx * (A11.y - A10.y);
                float tb0 = B00.x + wx * (B01.x - B00.x);
                float bb0 = B10.x + wx * (B11.x - B10.x);
                float tb1 = B00.y + wx * (B01.y - B00.y);
                float bb1 = B10.y + wx * (B11.y - B10.y);

                r[0][j] = ta0 + wy * (ba0 - ta0);
                r[1][j] = ta1 + wy * (ba1 - ta1);
                r[2][j] = tb0 + wy * (bb0 - tb0);
                r[3][j] = tb1 + wy * (bb1 - tb1);
            }

            int prow = (ty0 + py + i * 16) * PW + tx0 + 2 * u;
            #pragma unroll
            for (int ch = 0; ch < 4; ch++)
                *(float2*)(o0 + (size_t)ch * PHW + prow)
                    = make_float2(r[ch][0], r[ch][1]);
        }

        if (st < NST - 1) {
            __syncthreads();
            fill_sts((st & 1) ? bufA : bufB);
            if (st + 2 < NST) fill_ldg(st + 2);
            __syncthreads();
        }
    }
}

extern "C" void kernel_launch(void* const* d_in, const int* in_sizes, int n_in,
                              void* d_out, int out_size)
{
    const float* x   = (const float*)d_in[0];
    const float* phi = (const float*)d_in[1];
    float* out = (float*)d_out;

    const int smem_bytes = 2 * TILE_U2 * sizeof(uint2);   // 61440 B
    static int configured = -1;
    if (configured < 0) {
        cudaFuncSetAttribute(pull_h4p_kernel,
                             cudaFuncAttributeMaxDynamicSharedMemorySize,
                             smem_bytes);
        configured = 1;
    }

    dim3 grid(PW / TW, PH / TH, PB);   // 8 x 16 x 8 = 1024 blocks
    pull_h4p_kernel<<<grid, NT, smem_bytes>>>(x, phi, out);
}

// round 11
// speedup vs baseline: 1.3648x; 1.0557x over previous
#include <cuda_runtime.h>
#include <cuda_fp16.h>

// Pull_37091337568590, R11: R10 (fp16 channel-quad tiles, x-paired pixels)
// + single barrier per stage (fill of next stage overlaps blend of current)
// + streaming (__stcs) output stores to keep L2 for halo reuse.
// x: [8,16,512,512] f32, phi: [8,2,512,512] f32, out: [8,16,512,512] f32.

#define PB 8
#define PC 16
#define PH 512
#define PW 512
#define PHW (PH * PW)

#define TW 64
#define TH 32
#define HR 8
#define SW (TW + 2 * HR)       // 80 pixels per tile row
#define SH (TH + 2 * HR)       // 48 rows
#define SU 80                  // row stride in uint2
#define TILE_U2 (SH * SU)      // 3840 uint2 per buffer (30720 B)
#define NT 512
#define NRI 2                  // row iterations per thread (x2 px each)
#define NST 4                  // 4 channel-quad stages
#define FSLOTS (SH * (SW / 4)) // 960 float4 fill slots

__device__ __forceinline__ unsigned pk(float a, float b) {
    __half2 h = __floats2half2_rn(a, b);
    return *(unsigned*)&h;
}
__device__ __forceinline__ float2 up(unsigned u) {
    return __half22float2(*(__half2*)&u);
}

__global__ __launch_bounds__(NT, 2)
void pull_h4s_kernel(const float* __restrict__ x,
                     const float* __restrict__ phi,
                     float* __restrict__ out)
{
    extern __shared__ uint2 smemu[];
    uint2* bufA = smemu;
    uint2* bufB = smemu + TILE_U2;

    const int tx0 = blockIdx.x * TW;
    const int ty0 = blockIdx.y * TH;
    const int b   = blockIdx.z;
    const int tid = threadIdx.x;

    const int u  = tid & 31;         // x-pair index: pixels 2u, 2u+1
    const int py = tid >> 5;         // 0..15

    const float* __restrict__ phiy = phi + (size_t)b * 2 * PHW;
    const float* __restrict__ phix = phiy + PHW;
    const float* __restrict__ xb   = x   + (size_t)b * PC * PHW;
    float* __restrict__ ob         = out + (size_t)b * PC * PHW;

    // ---- per-pixel coords in registers: 2 row-iters x 2 px ----
    unsigned sel[NRI * 2];
    float    fwy[NRI * 2], fwx[NRI * 2];
    #pragma unroll
    for (int i = 0; i < NRI; i++) {
        int ly = py + i * 16;
        int h  = ty0 + ly;
        int wb = tx0 + 2 * u;
        int p  = h * PW + wb;

        float2 dy2 = __ldg((const float2*)(phiy + p));
        float2 dx2 = __ldg((const float2*)(phix + p));

        #pragma unroll
        for (int j = 0; j < 2; j++) {
            float cy = (j ? dy2.y : dy2.x) + (float)h;
            float cx = (j ? dx2.y : dx2.x) + (float)(wb + j);
            float y0f = floorf(cy);
            float x0f = floorf(cx);
            int k = i * 2 + j;
            fwy[k] = cy - y0f;
            fwx[k] = cx - x0f;

            int y0 = (int)y0f;
            int x0 = (int)x0f;
            int sy = y0 - (ty0 - HR);
            int sx = x0 - (tx0 - HR);

            if ((unsigned)sy < (SH - 1) && (unsigned)sx < (SW - 1)) {
                sel[k] = (unsigned)((sy * SU + sx) * 8);    // byte offset (uint2)
            } else {
                sel[k] = 0x80000000u | ((unsigned)(y0 & (PH - 1)) << 9)
                                     |  (unsigned)(x0 & (PW - 1));
            }
        }
    }

    // ---- fill mapping: 960 float4 slots, 2 passes ----
    const int slot0 = tid;
    const int slot1 = tid + NT;
    const bool act1 = (slot1 < FSLOTS);
    const int r0 = slot0 / 20, c40 = slot0 - r0 * 20;
    const int r1 = slot1 / 20, c41 = slot1 - r1 * 20;
    const int goff0 = (((ty0 - HR + r0) & (PH - 1)) * PW)
                    +  ((tx0 - HR + c40 * 4) & (PW - 1));
    const int goff1 = (((ty0 - HR + r1) & (PH - 1)) * PW)
                    +  ((tx0 - HR + c41 * 4) & (PW - 1));
    const int d0 = r0 * SU + c40 * 4;
    const int d1 = r1 * SU + c41 * 4;

    uint2 h0[4], h1[4];                      // packed fill regs (held one stage)

    auto fill_ldg = [&](int st) {
        const float* base = xb + (size_t)(4 * st) * PHW;
        {
            float4 a  = *(const float4*)(base + goff0);
            float4 bq = *(const float4*)(base + PHW + goff0);
            float4 c  = *(const float4*)(base + 2 * PHW + goff0);
            float4 d  = *(const float4*)(base + 3 * PHW + goff0);
            h0[0] = make_uint2(pk(a.x, bq.x), pk(c.x, d.x));
            h0[1] = make_uint2(pk(a.y, bq.y), pk(c.y, d.y));
            h0[2] = make_uint2(pk(a.z, bq.z), pk(c.z, d.z));
            h0[3] = make_uint2(pk(a.w, bq.w), pk(c.w, d.w));
        }
        if (act1) {
            float4 a  = *(const float4*)(base + goff1);
            float4 bq = *(const float4*)(base + PHW + goff1);
            float4 c  = *(const float4*)(base + 2 * PHW + goff1);
            float4 d  = *(const float4*)(base + 3 * PHW + goff1);
            h1[0] = make_uint2(pk(a.x, bq.x), pk(c.x, d.x));
            h1[1] = make_uint2(pk(a.y, bq.y), pk(c.y, d.y));
            h1[2] = make_uint2(pk(a.z, bq.z), pk(c.z, d.z));
            h1[3] = make_uint2(pk(a.w, bq.w), pk(c.w, d.w));
        }
    };
    auto fill_sts = [&](uint2* buf) {
        *(uint4*)(buf + d0)     = make_uint4(h0[0].x, h0[0].y, h0[1].x, h0[1].y);
        *(uint4*)(buf + d0 + 2) = make_uint4(h0[2].x, h0[2].y, h0[3].x, h0[3].y);
        if (act1) {
            *(uint4*)(buf + d1)     = make_uint4(h1[0].x, h1[0].y, h1[1].x, h1[1].y);
            *(uint4*)(buf + d1 + 2) = make_uint4(h1[2].x, h1[2].y, h1[3].x, h1[3].y);
        }
    };

    // ---- prologue: stage 0 staged, stage 1 LDG in flight ----
    fill_ldg(0);
    fill_sts(bufA);
    fill_ldg(1);
    __syncthreads();

    // ---- stage loop: ONE barrier per stage; fill(st+1) overlaps blend(st) --
    #pragma unroll
    for (int st = 0; st < NST; st++) {
        const uint2* __restrict__ cur = (st & 1) ? bufB : bufA;
        const float* __restrict__ c0 = xb + (size_t)(4 * st) * PHW;
        float* __restrict__ o0       = ob + (size_t)(4 * st) * PHW;

        // stage-top barrier (prologue sync for st==0) already passed:
        // write next stage's tile (other buffer) while blending this one.
        if (st + 1 < NST) {
            fill_sts((st & 1) ? bufA : bufB);    // stage st+1 (regs from earlier)
            if (st + 2 < NST) fill_ldg(st + 2);  // prefetch stage st+2
        }

        #pragma unroll
        for (int i = 0; i < NRI; i++) {
            float r[4][2];                       // [channel][px in pair]
            #pragma unroll
            for (int j = 0; j < 2; j++) {
                int k = i * 2 + j;
                unsigned sl = sel[k];
                float wy = fwy[k];
                float wx = fwx[k];

                float2 A00, A01, A10, A11;       // ch 0,1
                float2 B00, B01, B10, B11;       // ch 2,3
                if (!(sl & 0x80000000u)) {
                    const uint2* t = (const uint2*)((const char*)cur + sl);
                    uint2 v00 = t[0], v01 = t[1], v10 = t[SU], v11 = t[SU + 1];
                    A00 = up(v00.x); B00 = up(v00.y);
                    A01 = up(v01.x); B01 = up(v01.y);
                    A10 = up(v10.x); B10 = up(v10.y);
                    A11 = up(v11.x); B11 = up(v11.y);
                } else {
                    int y0 = (int)((sl >> 9) & (PH - 1));
                    int x0 = (int)(sl & (PW - 1));
                    int y1 = (y0 + 1) & (PH - 1);
                    int x1 = (x0 + 1) & (PW - 1);
                    int a = y0 * PW + x0, bq = y0 * PW + x1;
                    int cq = y1 * PW + x0, d = y1 * PW + x1;
                    A00 = make_float2(__ldg(c0 + a),            __ldg(c0 + PHW + a));
                    A01 = make_float2(__ldg(c0 + bq),           __ldg(c0 + PHW + bq));
                    A10 = make_float2(__ldg(c0 + cq),           __ldg(c0 + PHW + cq));
                    A11 = make_float2(__ldg(c0 + d),            __ldg(c0 + PHW + d));
                    B00 = make_float2(__ldg(c0 + 2 * PHW + a),  __ldg(c0 + 3 * PHW + a));
                    B01 = make_float2(__ldg(c0 + 2 * PHW + bq), __ldg(c0 + 3 * PHW + bq));
                    B10 = make_float2(__ldg(c0 + 2 * PHW + cq), __ldg(c0 + 3 * PHW + cq));
                    B11 = make_float2(__ldg(c0 + 2 * PHW + d),  __ldg(c0 + 3 * PHW + d));
                }

                float ta0 = A00.x + wx * (A01.x - A00.x);
                float ba0 = A10.x + wx * (A11.x - A10.x);
                float ta1 = A00.y + wx * (A01.y - A00.y);
                float ba1 = A10.y + wx * (A11.y - A10.y);
                float tb0 = B00.x + wx * (B01.x - B00.x);
                float bb0 = B10.x + wx * (B11.x - B10.x);
                float tb1 = B00.y + wx * (B01.y - B00.y);
                float bb1 = B10.y + wx * (B11.y - B10.y);

                r[0][j] = ta0 + wy * (ba0 - ta0);
                r[1][j] = ta1 + wy * (ba1 - ta1);
                r[2][j] = tb0 + wy * (bb0 - tb0);
                r[3][j] = tb1 + wy * (bb1 - tb1);
            }

            int prow = (ty0 + py + i * 16) * PW + tx0 + 2 * u;
            #pragma unroll
            for (int ch = 0; ch < 4; ch++)
                __stcs((float2*)(o0 + (size_t)ch * PHW + prow),
                       make_float2(r[ch][0], r[ch][1]));
        }

        if (st + 1 < NST)
            __syncthreads();   // fill(st+1) visible; readers of cur done
    }
}

extern "C" void kernel_launch(void* const* d_in, const int* in_sizes, int n_in,
                              void* d_out, int out_size)
{
    const float* x   = (const float*)d_in[0];
    const float* phi = (const float*)d_in[1];
    float* out = (float*)d_out;

    const int smem_bytes = 2 * TILE_U2 * sizeof(uint2);   // 61440 B
    static int configured = -1;
    if (configured < 0) {
        cudaFuncSetAttribute(pull_h4s_kernel,
                             cudaFuncAttributeMaxDynamicSharedMemorySize,
                             smem_bytes);
        configured = 1;
    }

    dim3 grid(PW / TW, PH / TH, PB);   // 8 x 16 x 8 = 1024 blocks
    pull_h4s_kernel<<<grid, NT, smem_bytes>>>(x, phi, out);
}